// round 3
// baseline (speedup 1.0000x reference)
#include <cuda_runtime.h>

#define ORDER 32
#define EPSV 1e-5f

typedef unsigned long long u64;

// ---- packed f32x2 helpers (sm_103a packed FMA) ----
__device__ __forceinline__ u64 fma2(u64 a, u64 b, u64 c) {
    u64 d;
    asm("fma.rn.f32x2 %0, %1, %2, %3;" : "=l"(d) : "l"(a), "l"(b), "l"(c));
    return d;
}
__device__ __forceinline__ u64 add2(u64 a, u64 b) {
    u64 d;
    asm("add.rn.f32x2 %0, %1, %2;" : "=l"(d) : "l"(a), "l"(b));
    return d;
}
__device__ __forceinline__ u64 mul2(u64 a, u64 b) {
    u64 d;
    asm("mul.rn.f32x2 %0, %1, %2;" : "=l"(d) : "l"(a), "l"(b));
    return d;
}
__device__ __forceinline__ u64 neg2(u64 a) {
    return a ^ 0x8000000080000000ULL;  // flip both sign bits (alu pipe)
}
__device__ __forceinline__ u64 pack2(float lo, float hi) {
    u64 r;
    asm("mov.b64 %0, {%1, %2};" : "=l"(r) : "f"(lo), "f"(hi));
    return r;
}
__device__ __forceinline__ void unpack2(u64 v, float& lo, float& hi) {
    asm("mov.b64 {%0, %1}, %2;" : "=f"(lo), "=f"(hi) : "l"(v));
}
__device__ __forceinline__ float rcp_fast(float x) {
    float r;
    asm("rcp.approx.f32 %0, %1;" : "=f"(r) : "f"(x));
    return r;
}

__global__ __launch_bounds__(128, 4)
void levinson_kernel3(const u64* __restrict__ pAC2,  // [33, T/2] packed frame pairs
                      u64* __restrict__ out2,        // [32, T/2]
                      int Th)                        // T/2
{
    int t = blockIdx.x * blockDim.x + threadIdx.x;
    if (t >= Th) return;

    const u64 ONE2 = 0x3f8000003f800000ULL;  // (1.0f, 1.0f)

    u64 ac[ORDER + 1];   // two adjacent frames per thread, packed
    u64 lp[ORDER];

    // invE = 1 / ac[0] per lane (ac[0] == 1 in this dataset, but stay general)
    {
        u64 a0 = pAC2[t];
        float e0, e1;
        unpack2(a0, e0, e1);
        ac[0] = a0;  // not needed again; ptxas will kill it
        float i0 = rcp_fast(e0);
        float i1 = rcp_fast(e1);
        ac[0] = pack2(i0, i1);  // reuse slot 0 as invE storage? no—keep separate
    }
    u64 invE2;
    {
        // redo cleanly (slot reuse above is confusing; let compiler handle liveness)
        u64 a0 = pAC2[t];
        float e0, e1;
        unpack2(a0, e0, e1);
        invE2 = pack2(rcp_fast(e0), rcp_fast(e1));
    }

#pragma unroll
    for (int i = 0; i < ORDER; i++) {
        // lazy-load next lag (coalesced 8B loads)
        ac[i + 1] = pAC2[(i + 1) * Th + t];

        // acc = ac[i+1] + sum_{j<i} lp[j]*ac[i-j], 4-way split accumulators
        u64 acc0 = ac[i + 1];
        u64 acc1 = 0ull, acc2 = 0ull, acc3 = 0ull;
#pragma unroll
        for (int j = 0; j < i; j += 4) {
            acc0 = fma2(lp[j], ac[i - j], acc0);
            if (j + 1 < i) acc1 = fma2(lp[j + 1], ac[i - j - 1], acc1);
            if (j + 2 < i) acc2 = fma2(lp[j + 2], ac[i - j - 2], acc2);
            if (j + 3 < i) acc3 = fma2(lp[j + 3], ac[i - j - 3], acc3);
        }
        u64 acc = acc0;
        if (i > 1) acc1 = add2(acc1, (i > 3) ? acc3 : 0ull);
        if (i > 2) acc0 = add2(acc0, acc2);
        if (i > 1) acc = add2((i > 2) ? acc0 : acc0, acc1);
        if (i == 1) acc = acc0;
        // (for i<=1 acc==acc0 already)

        // ki = acc * invE (invE was ready since last iteration -> rcp off the chain)
        u64 ki2  = mul2(acc, invE2);
        u64 nki2 = neg2(ki2);

        // c = 1 - ki^2, clip, then invE *= 1/c  (off critical path of next dot)
        u64 c2 = fma2(nki2, ki2, ONE2);
        float c0, c1;
        unpack2(c2, c0, c1);
        c0 = fmaxf(c0, EPSV);
        c1 = fmaxf(c1, EPSV);
        invE2 = mul2(invE2, pack2(rcp_fast(c0), rcp_fast(c1)));

        // lp[j] = lp[j] - ki * lp_old[i-1-j]  (symmetric in-place pair update)
#pragma unroll
        for (int j = 0; j < i / 2; j++) {
            u64 a = lp[j];
            u64 b = lp[i - 1 - j];
            lp[j]         = fma2(nki2, b, a);
            lp[i - 1 - j] = fma2(nki2, a, b);
        }
        if (i & 1) {
            int m = (i - 1) / 2;
            lp[m] = fma2(nki2, lp[m], lp[m]);
        }

        lp[i] = nki2;
    }

#pragma unroll
    for (int i = 0; i < ORDER; i++) {
        out2[i * Th + t] = lp[i];
    }
}

extern "C" void kernel_launch(void* const* d_in, const int* in_sizes, int n_in,
                              void* d_out, int out_size)
{
    const u64* pAC2 = (const u64*)d_in[0];
    u64* out2 = (u64*)d_out;
    int T = in_sizes[0] / (ORDER + 1);   // pAC is [1, N+1, T]; T = 2^20 (even)
    int Th = T / 2;

    int threads = 128;
    int blocks = (Th + threads - 1) / threads;
    levinson_kernel3<<<blocks, threads>>>(pAC2, out2, Th);
}

// round 4
// speedup vs baseline: 1.0244x; 1.0244x over previous
#include <cuda_runtime.h>

#define ORDER 32
#define EPSV 1e-5f

typedef unsigned long long u64;

// ---- packed f32x2 helpers (sm_103a packed FMA) ----
__device__ __forceinline__ u64 fma2(u64 a, u64 b, u64 c) {
    u64 d;
    asm("fma.rn.f32x2 %0, %1, %2, %3;" : "=l"(d) : "l"(a), "l"(b), "l"(c));
    return d;
}
__device__ __forceinline__ u64 add2(u64 a, u64 b) {
    u64 d;
    asm("add.rn.f32x2 %0, %1, %2;" : "=l"(d) : "l"(a), "l"(b));
    return d;
}
__device__ __forceinline__ u64 mul2(u64 a, u64 b) {
    u64 d;
    asm("mul.rn.f32x2 %0, %1, %2;" : "=l"(d) : "l"(a), "l"(b));
    return d;
}
__device__ __forceinline__ u64 neg2(u64 a) {
    return a ^ 0x8000000080000000ULL;  // flip both sign bits (alu pipe)
}
__device__ __forceinline__ u64 pack2(float lo, float hi) {
    u64 r;
    asm("mov.b64 %0, {%1, %2};" : "=l"(r) : "f"(lo), "f"(hi));
    return r;
}
__device__ __forceinline__ void unpack2(u64 v, float& lo, float& hi) {
    asm("mov.b64 {%0, %1}, %2;" : "=f"(lo), "=f"(hi) : "l"(v));
}
__device__ __forceinline__ float rcp_fast(float x) {
    float r;
    asm("rcp.approx.f32 %0, %1;" : "=f"(r) : "f"(x));
    return r;
}

// 64-thread blocks, min 7 blocks/SM -> reg cap 146 (>= ~140 demand, NO spills),
// 14 warps/SM (3.5/SMSP) vs 12 previously.
__global__ __launch_bounds__(64, 7)
void levinson_kernel4(const u64* __restrict__ pAC2,  // [33, T/2] packed frame pairs
                      u64* __restrict__ out2,        // [32, T/2]
                      int Th)                        // T/2
{
    int t = blockIdx.x * blockDim.x + threadIdx.x;
    if (t >= Th) return;

    const u64 ONE2 = 0x3f8000003f800000ULL;  // (1.0f, 1.0f)

    u64 ac[ORDER + 1];   // two adjacent frames per thread, packed
    u64 lp[ORDER];

    // invE = 1 / ac[0] per lane (general, even though r0 == 1 in this dataset)
    u64 invE2;
    {
        ac[0] = pAC2[t];
        float e0, e1;
        unpack2(ac[0], e0, e1);
        invE2 = pack2(rcp_fast(e0), rcp_fast(e1));
    }

#pragma unroll
    for (int i = 0; i < ORDER; i++) {
        // lazy-load next lag (coalesced 8B loads; ptxas hoists/schedules)
        ac[i + 1] = pAC2[(i + 1) * Th + t];

        // acc = ac[i+1] + sum_{j<i} lp[j]*ac[i-j], 4-way split accumulators
        u64 acc0 = ac[i + 1];
        u64 acc1 = 0ull, acc2 = 0ull, acc3 = 0ull;
#pragma unroll
        for (int j = 0; j < i; j += 4) {
            acc0 = fma2(lp[j], ac[i - j], acc0);
            if (j + 1 < i) acc1 = fma2(lp[j + 1], ac[i - j - 1], acc1);
            if (j + 2 < i) acc2 = fma2(lp[j + 2], ac[i - j - 2], acc2);
            if (j + 3 < i) acc3 = fma2(lp[j + 3], ac[i - j - 3], acc3);
        }
        // fold the tree (guards keep instr count minimal for small i)
        if (i > 2) acc0 = add2(acc0, acc2);
        if (i > 3) acc1 = add2(acc1, acc3);
        if (i > 1) acc0 = add2(acc0, acc1);

        // ki = acc * invE  (invE ready since last iteration -> rcp off the chain)
        u64 ki2  = mul2(acc0, invE2);
        u64 nki2 = neg2(ki2);

        // c = clip(1 - ki^2), invE *= 1/c  (off the critical path of next dot)
        u64 c2 = fma2(nki2, ki2, ONE2);
        float c0, c1;
        unpack2(c2, c0, c1);
        c0 = fmaxf(c0, EPSV);
        c1 = fmaxf(c1, EPSV);
        invE2 = mul2(invE2, pack2(rcp_fast(c0), rcp_fast(c1)));

        // lp[j] = lp[j] - ki * lp_old[i-1-j]  (symmetric in-place pair update)
#pragma unroll
        for (int j = 0; j < i / 2; j++) {
            u64 a = lp[j];
            u64 b = lp[i - 1 - j];
            lp[j]         = fma2(nki2, b, a);
            lp[i - 1 - j] = fma2(nki2, a, b);
        }
        if (i & 1) {
            int m = (i - 1) / 2;
            lp[m] = fma2(nki2, lp[m], lp[m]);
        }

        lp[i] = nki2;
    }

#pragma unroll
    for (int i = 0; i < ORDER; i++) {
        out2[i * Th + t] = lp[i];
    }
}

extern "C" void kernel_launch(void* const* d_in, const int* in_sizes, int n_in,
                              void* d_out, int out_size)
{
    const u64* pAC2 = (const u64*)d_in[0];
    u64* out2 = (u64*)d_out;
    int T = in_sizes[0] / (ORDER + 1);   // pAC is [1, N+1, T]; T = 2^20 (even)
    int Th = T / 2;

    int threads = 64;
    int blocks = (Th + threads - 1) / threads;
    levinson_kernel4<<<blocks, threads>>>(pAC2, out2, Th);
}